// round 7
// baseline (speedup 1.0000x reference)
#include <cuda_runtime.h>
#include <math.h>

#ifndef M_PI
#define M_PI 3.14159265358979323846
#endif

#define N_TOT   8388608
#define W       882
#define WP      884
#define NB      9510
#define REM     788
#define MCH     64
#define NCH     149
#define LASTS   38
#define GLEN    19
#define NG      8
#define AOFF    860
#define FSZ     1756
#define SRATE   44100.0
#define LBQ     64
#define BQB     128
#define BQT     1024
#define PREPB   9
#define CBLK    130

// ---- scratch ----
__device__ float  g_wt[W];
__device__ float  g_dstate[NCH * WP];
__device__ float  g_vstart[NCH * WP];
__device__ float  g_sA[NG * WP];
__device__ float  g_sB[NG * WP];
__device__ float  g_ks[N_TOT];
__device__ float2 g_blk[BQB];
__device__ double g_Ms[18][4];           // M^(64 * 2^s), s=0..17
__device__ float  g_par[12];             // 0:d2 1:fa2 2..6:bq 7:ia 8:ir 9:sg
__device__ float  g_Kt[GLEN * 256];      // reversed taps S^(64k), k=1..19
__device__ float  g_Kt2[2 * 384];        // k=38, k=76
__device__ int    g_Kwk[GLEN + 1], g_Koff[GLEN + 1];
__device__ int    g_K2wk[2], g_K2off[2];
__device__ unsigned g_bar;

// ---- grid barrier (all blocks co-resident; grid <= 148) ----
__device__ __forceinline__ void gbar(unsigned target) {
    __threadfence();
    __syncthreads();
    if (threadIdx.x == 0) {
        atomicAdd(&g_bar, 1u);
        while (*(volatile unsigned*)&g_bar < target) { }
    }
    __syncthreads();
    __threadfence();
}

// geometry of truncated kernel for S^(64k), window folded mod W
__device__ __forceinline__ void kgeom2(int k, int& c0e, int& wk, int& jb) {
    int m = 64 * k;
    int hw = (int)ceil(21.0 * sqrt((double)k));
    int c0 = m / 2 - hw;
    wk = (2 * hw + 4) & ~3;
    int red = (c0 / W) * W;
    int ce = c0 - red;
    ce -= (ce + wk - 1) & 3;       // force (ce+wk) % 4 == 1
    c0e = ce;
    jb = ce + red;
}

__device__ __forceinline__ float ftanh2(float x2) {
    float e = __expf(x2);
    return __fdividef(e - 1.0f, e + 1.0f);
}

// f[] circular extension: f[t] = v[(t - AOFF) mod W], t in [0, FSZ)
__device__ __forceinline__ void f_write(float* f, int p, float v) {
    f[p + AOFF] = v;
    if (p >= W - AOFF) f[p - (W - AOFF)] = v;      // W-AOFF = 22
    if (p < FSZ - (W + AOFF)) f[p + W + AOFF] = v; // p < 14
}

__device__ __forceinline__ void conv_into(const float* __restrict__ f,
                                          const float* __restrict__ Ks,
                                          int wk, int off, int o0, float* acc) {
    int b0 = o0 + off;
    float4 da = *(const float4*)&f[b0];
    #pragma unroll 2
    for (int jj = 0; jj < wk; jj += 4) {
        float4 ka = *(const float4*)&Ks[jj];
        float4 db = *(const float4*)&f[b0 + jj + 4];
        acc[0] = fmaf(ka.x, da.x, acc[0]); acc[0] = fmaf(ka.y, da.y, acc[0]);
        acc[0] = fmaf(ka.z, da.z, acc[0]); acc[0] = fmaf(ka.w, da.w, acc[0]);
        acc[1] = fmaf(ka.x, da.y, acc[1]); acc[1] = fmaf(ka.y, da.z, acc[1]);
        acc[1] = fmaf(ka.z, da.w, acc[1]); acc[1] = fmaf(ka.w, db.x, acc[1]);
        acc[2] = fmaf(ka.x, da.z, acc[2]); acc[2] = fmaf(ka.y, da.w, acc[2]);
        acc[2] = fmaf(ka.z, db.x, acc[2]); acc[2] = fmaf(ka.w, db.y, acc[2]);
        acc[3] = fmaf(ka.x, da.w, acc[3]); acc[3] = fmaf(ka.y, db.x, acc[3]);
        acc[3] = fmaf(ka.z, db.y, acc[3]); acc[3] = fmaf(ka.w, db.z, acc[3]);
        da = db;
    }
}

// ============================================================
// Karplus runner (2 steps / barrier round)
// ============================================================
template<int NR, bool P1>
__device__ __forceinline__ void ks_run2(const float* __restrict__ xin,
                                        float* __restrict__ uout,
                                        float* __restrict__ op,
                                        float& a,
                                        float (*bsh)[W], float (*ush)[W],
                                        bool act, int i, int im1, int im2,
                                        float d2, float fa2) {
    float xa[2], xb[2];
    #pragma unroll
    for (int q = 0; q < 2; q++) {
        xa[q] = act ? xin[(size_t)(2 * q) * W] : 0.f;
        xb[q] = act ? xin[(size_t)(2 * q + 1) * W] : 0.f;
    }
    #pragma unroll 2
    for (int r = 0; r < NR; r++) {
        float x0 = xa[r & 1], x1 = xb[r & 1];
        if (act && r + 2 < NR) {
            xa[r & 1] = xin[(size_t)(2 * r + 4) * W];
            xb[r & 1] = xin[(size_t)(2 * r + 5) * W];
        }
        float u0, u1;
        if (P1) {
            u0 = ftanh2(fa2 * x0);
            u1 = ftanh2(fa2 * x1);
            if (act) {
                uout[(size_t)(2 * r) * W] = u0;
                uout[(size_t)(2 * r + 1) * W] = u1;
            }
        } else { u0 = x0; u1 = x1; }

        float bb = a + u0;
        if (act) { bsh[r & 1][i] = bb; ush[r & 1][i] = u1; }
        __syncthreads();
        if (act) {
            float bm1 = bsh[r & 1][im1], bm2 = bsh[r & 1][im2];
            float u1m1 = ush[r & 1][im1];
            float a1  = d2 * (bb + bm1);
            float a1m = d2 * (bm1 + bm2);
            float a2  = d2 * ((a1 + u1) + (a1m + u1m1));
            if (!P1) {
                op[(size_t)(2 * r) * W] = a1;
                op[(size_t)(2 * r + 1) * W] = a2;
            }
            a = a2;
        }
    }
}

// ============================================================
// Kernel 1: fused prep (blocks 0..8) + ks_pass1 (blocks 9..157)
// ============================================================
struct SmemP1 { float bsh[2][W]; float ush[2][W]; };
struct SmemWT { float xs[898]; float ys[898]; float2 sv[128]; float Pw[7][4]; float cf[10]; };

__global__ void __launch_bounds__(896) ks1_prep(const float* __restrict__ fb,
                                                float* __restrict__ uscr,
                                                const float* __restrict__ wavetable,
                                                const float* __restrict__ h,
                                                const float* __restrict__ envp,
                                                const float* __restrict__ lp2) {
    __shared__ union { SmemP1 p1; SmemWT wt; } sm;
    int b = blockIdx.x, t = threadIdx.x;

    if (b >= PREPB) {
        // ---------------- pass1: zero-init chunk runs + tanh precompute
        int c = b - PREPB;
        int i = t;
        bool act = i < W;
        int im1 = (i == 0) ? (W - 1) : (i - 1);
        int im2 = (i <= 1) ? (i + W - 2) : (i - 2);
        float dec = fminf(fmaxf(h[0] * 0.1f + 0.9f, 0.9f), 0.999f);
        float d2 = dec * 0.5f;
        float fa2 = 2.0f * h[3];

        float a = 0.0f;
        const float* fp = fb   + (size_t)c * MCH * W + i;
        float*       up = uscr + (size_t)c * MCH * W + i;
        if (c < NCH - 1) {
            ks_run2<MCH / 2, true>(fp, up, nullptr, a, sm.p1.bsh, sm.p1.ush,
                                   act, i, im1, im2, d2, fa2);
            if (act) g_dstate[c * WP + i] = a;
        } else {
            ks_run2<LASTS / 2, true>(fp, up, nullptr, a, sm.p1.bsh, sm.p1.ush,
                                     act, i, im1, im2, d2, fa2);
        }
        return;
    }

    if (b >= 2 && b <= 7) {
        // ---------------- K table rows k=1..19 (4864 taps)
        int idx = (b - 2) * 896 + t;
        if (idx < GLEN * 256) {
            double decay = (double)h[0] / 10.0 + 0.9;
            decay = fmin(fmax(decay, 0.9), 0.999);
            double ld2 = log(decay * 0.5);
            int k = idx / 256 + 1;
            int jj = idx % 256;
            int c0e, wk, jb; kgeom2(k, c0e, wk, jb);
            int m = 64 * k;
            float val = 0.0f;
            if (jj < wk) {
                int j = jb + wk - 1 - jj;
                if (j >= 0 && j <= m) {
                    double lg = lgamma((double)(m + 1)) - lgamma((double)(j + 1))
                              - lgamma((double)(m - j + 1)) + (double)m * ld2;
                    val = (float)exp(lg);
                }
            }
            g_Kt[idx] = val;
        }
        return;
    }

    if (b == 8) {
        // ---------------- K table rows k=38, 76 (2 x 384)
        int idx = t;
        if (idx < 2 * 384) {
            double decay = (double)h[0] / 10.0 + 0.9;
            decay = fmin(fmax(decay, 0.9), 0.999);
            double ld2 = log(decay * 0.5);
            int s = idx / 384;
            int jj = idx % 384;
            int k = 38 << s;
            int c0e, wk, jb; kgeom2(k, c0e, wk, jb);
            int m = 64 * k;
            float val = 0.0f;
            if (jj < wk) {
                int j = jb + wk - 1 - jj;
                if (j >= 0 && j <= m) {
                    double lg = lgamma((double)(m + 1)) - lgamma((double)(j + 1))
                              - lgamma((double)(m - j + 1)) + (double)m * ld2;
                    val = (float)exp(lg);
                }
            }
            g_Kt2[idx] = val;
        }
        return;
    }

    if (b == 0) {
        // ---------------- scalars
        if (t >= 1 && t <= GLEN) {
            int c0e, wk, jb; kgeom2(t, c0e, wk, jb);
            g_Kwk[t] = wk;
            g_Koff[t] = AOFF + 1 - c0e - wk;
        }
        if (t == 20 || t == 21) {
            int lvl = t - 20;
            int c0e, wk, jb; kgeom2(38 << lvl, c0e, wk, jb);
            g_K2wk[lvl] = wk;
            g_K2off[lvl] = AOFF + 1 - c0e - wk;
        }
        if (t != 0) return;

        g_bar = 0;

        double decay = (double)h[0] / 10.0 + 0.9;
        decay = fmin(fmax(decay, 0.9), 0.999);

        double h5 = h[5], h6 = h[6];
        double brf = h5 * SRATE / 4.0; brf = fmin(fmax(brf, 100.0), SRATE / 2.0 - 1.0);
        double brq = fmin(fmax(h6, 0.1), 0.999);
        double w0b = 2.0 * M_PI * brf / SRATE, alb = sin(w0b) / (2.0 * brq), cwb = cos(w0b);
        double a0b = 1.0 + alb;
        double bb0 = 1.0 / a0b, bb1 = (-2.0 * cwb) / a0b, bb2 = 1.0 / a0b;
        double ba1 = (-2.0 * cwb) / a0b, ba2 = (1.0 - alb) / a0b;

        // M^(64 * 2^s), s=0..17
        {
            double m00 = -ba1, m01 = -ba2, m10 = 1.0, m11 = 0.0;
            for (int s = 0; s < 6; s++) {                    // -> M^64
                double n00 = m00 * m00 + m01 * m10, n01 = m00 * m01 + m01 * m11;
                double n10 = m10 * m00 + m11 * m10, n11 = m10 * m01 + m11 * m11;
                m00 = n00; m01 = n01; m10 = n10; m11 = n11;
            }
            for (int s = 0; s < 18; s++) {
                g_Ms[s][0] = m00; g_Ms[s][1] = m01; g_Ms[s][2] = m10; g_Ms[s][3] = m11;
                double n00 = m00 * m00 + m01 * m10, n01 = m00 * m01 + m01 * m11;
                double n10 = m10 * m00 + m11 * m10, n11 = m10 * m01 + m11 * m11;
                m00 = n00; m01 = n01; m10 = n10; m11 = n11;
            }
        }

        double nD = (double)N_TOT;
        double attack  = 1.0 + (double)envp[0] * 0.1 * nD;
        double release = 1.0 + (double)envp[2] * 0.1 * nD;
        double sustain = fmin(fmax((double)envp[1], 0.0), 1.0);

        g_par[0] = (float)(decay * 0.5);
        g_par[1] = (float)(2.0 * (double)h[3]);
        g_par[2] = (float)bb0; g_par[3] = (float)bb1; g_par[4] = (float)bb2;
        g_par[5] = (float)ba1; g_par[6] = (float)ba2;
        g_par[7] = (float)(1.0 / attack);
        g_par[8] = (float)(1.0 / release);
        g_par[9] = (float)(sustain * (double)h[4]);
        return;
    }

    // ---------------- b == 1: wavetable prefilter (t<128 active; all sync)
    {
        float* xs = sm.wt.xs; float* ys = sm.wt.ys;
        float2* sv = sm.wt.sv; float (*Pw)[4] = sm.wt.Pw; float* cf = sm.wt.cf;

        if (t < 128)
            for (int p = t; p < 896; p += 128) xs[2 + p] = (p < W) ? wavetable[p] : 0.0f;
        if (t < 2) { xs[t] = 0.0f; ys[t] = 0.0f; }

        if (t == 0) {
            double h1 = h[1], h2 = h[2];
            double lpf = h1 * SRATE / 4.0; lpf = fmin(fmax(lpf, 100.0), SRATE / 2.0 - 1.0);
            double lpq = fmin(fmax(h2, 0.1), 0.999);
            double w0 = 2.0 * M_PI * lpf / SRATE, al = sin(w0) / (2.0 * lpq), cw = cos(w0);
            double a0 = 1.0 + al;
            cf[0] = (float)(((1.0 - cw) * 0.5) / a0);
            cf[1] = (float)((1.0 - cw) / a0);
            cf[2] = cf[0];
            cf[3] = (float)((-2.0 * cw) / a0);
            cf[4] = (float)((1.0 - al) / a0);
            double c2 = 100.0 + (double)lp2[0] * 8000.0;
            double w02 = 2.0 * M_PI * c2 / SRATE, al2 = sin(w02) / (2.0 * 0.707), cw2 = cos(w02);
            double a02 = 1.0 + al2;
            cf[5] = (float)(((1.0 - cw2) * 0.5) / a02);
            cf[6] = (float)((1.0 - cw2) / a02);
            cf[7] = cf[5];
            cf[8] = (float)((-2.0 * cw2) / a02);
            cf[9] = (float)((1.0 - al2) / a02);
        }
        __syncthreads();

        #pragma unroll
        for (int f = 0; f < 2; f++) {
            float b0 = cf[5 * f + 0], b1 = cf[5 * f + 1], b2 = cf[5 * f + 2];
            float a1 = cf[5 * f + 3], a2 = cf[5 * f + 4];
            const float* in = (f == 0) ? xs : ys;
            int base = 2 + 7 * (t & 127);

            if (t < 128) {
                float y1 = 0.f, y2 = 0.f;
                #pragma unroll
                for (int i = 0; i < 7; i++) {
                    float cn = b0 * in[base + i] + b1 * in[base + i - 1] + b2 * in[base + i - 2];
                    float yn = cn - a1 * y1 - a2 * y2;
                    y2 = y1; y1 = yn;
                }
                sv[t] = make_float2(y1, y2);
            }
            if (t == 0) {
                double A00 = -(double)a1, A01 = -(double)a2, A10 = 1.0, A11 = 0.0;
                double q00 = A00*A00 + A01*A10, q01 = A00*A01 + A01*A11;
                double q10 = A10*A00 + A11*A10, q11 = A10*A01 + A11*A11;
                double r00 = q00*q00 + q01*q10, r01 = q00*q01 + q01*q11;
                double r10 = q10*q00 + q11*q10, r11 = q10*q01 + q11*q11;
                double s00 = r00*q00 + r01*q10, s01 = r00*q01 + r01*q11;
                double s10 = r10*q00 + r11*q10, s11 = r10*q01 + r11*q11;
                double m00 = s00*A00 + s01*A10, m01 = s00*A01 + s01*A11;
                double m10 = s10*A00 + s11*A10, m11 = s10*A01 + s11*A11;
                for (int s = 0; s < 7; s++) {
                    Pw[s][0] = (float)m00; Pw[s][1] = (float)m01;
                    Pw[s][2] = (float)m10; Pw[s][3] = (float)m11;
                    double n00 = m00*m00 + m01*m10, n01 = m00*m01 + m01*m11;
                    double n10 = m10*m00 + m11*m10, n11 = m10*m01 + m11*m11;
                    m00 = n00; m01 = n01; m10 = n10; m11 = n11;
                }
            }
            __syncthreads();

            for (int s = 0; s < 7; s++) {
                int off = 1 << s;
                float ax = 0.f, ay = 0.f;
                if (t < 128 && t >= off) {
                    float2 src = sv[t - off];
                    ax = Pw[s][0] * src.x + Pw[s][1] * src.y;
                    ay = Pw[s][2] * src.x + Pw[s][3] * src.y;
                }
                __syncthreads();
                if (t < 128) { sv[t].x += ax; sv[t].y += ay; }
                __syncthreads();
            }

            if (t < 128) {
                float py1 = 0.f, py2 = 0.f;
                if (t > 0) { py1 = sv[t - 1].x; py2 = sv[t - 1].y; }
                #pragma unroll
                for (int i = 0; i < 7; i++) {
                    float cn = b0 * in[base + i] + b1 * in[base + i - 1] + b2 * in[base + i - 2];
                    float yn = cn - a1 * py1 - a2 * py2;
                    py2 = py1; py1 = yn;
                    if (f == 0) ys[base + i] = yn;
                    else { int g = 7 * t + i; if (g < W) g_wt[g] = yn; }
                }
            }
            __syncthreads();
        }
    }
}

// ============================================================
// Kernel 2: fused combine (phase A + group KS-scan + phase C)
// 130 blocks x 256 threads, 4 grid barriers.
// ============================================================
__global__ void __launch_bounds__(256) ks_combine_all() {
    __shared__ __align__(16) float f[FSZ];
    __shared__ __align__(16) float Ks[384];
    int b = blockIdx.x, t = threadIdx.x;

    // ---------------- phase A: 8 groups in parallel (blocks 0..7)
    if (b < NG) {
        int g = b;
        for (int p = t; p < g_Kwk[1]; p += 256) Ks[p] = g_Kt[p];   // k=1 row
        int wk = g_Kwk[1], off = g_Koff[1];
        int c1 = g * GLEN;
        int len = (g == NG - 1) ? (NCH - (NG - 1) * GLEN) : GLEN;
        int cend  = c1 + len;
        int cendT = (g == NG - 1) ? (NCH - 1) : cend;

        int cbeg;
        if (g == 0) {
            for (int p = t; p < W; p += 256) {
                float v = g_wt[p];
                f_write(f, p, v);
                g_vstart[p] = v;
            }
            cbeg = 1;
        } else {
            for (int p = t; p < W; p += 256) {
                float v = g_dstate[c1 * WP + p];
                f_write(f, p, v);
                g_vstart[(c1 + 1) * WP + p] = v;
            }
            cbeg = c1 + 2;
        }
        __syncthreads();

        int o0 = t * 4;
        bool activ = o0 < W;
        float4 dv = make_float4(0.f, 0.f, 0.f, 0.f);
        if (activ) dv = *(const float4*)(g_dstate + (size_t)(cbeg - 1) * WP + o0);

        for (int c = cbeg; c <= cendT; c++) {
            float4 dnext = make_float4(0.f, 0.f, 0.f, 0.f);
            if (activ && c <= cendT - 1)
                dnext = *(const float4*)(g_dstate + (size_t)c * WP + o0);

            float acc[4] = {dv.x, dv.y, dv.z, dv.w};
            if (activ) conv_into(f, Ks, wk, off, o0, acc);
            __syncthreads();
            if (activ) {
                float* dst;
                if (c < cend) dst = g_vstart + (size_t)c * WP + o0;
                else dst = g_sA + (size_t)(g + 1) * WP + o0;    // X_1 (g=0) / Z_g
                #pragma unroll
                for (int e = 0; e < 4; e++) {
                    int p = o0 + e;
                    if (p < W) { f_write(f, p, acc[e]); dst[e] = acc[e]; }
                }
            }
            __syncthreads();
            dv = dnext;
        }
    }
    gbar(CBLK);

    // ---------------- phase B: KS scan over 7 group states, 3 levels
    for (int s = 0; s < 3; s++) {
        int off = 1 << s;
        if (b >= 1 && b <= 7) {
            const float* src = (s & 1) ? g_sB : g_sA;
            float*       dst = (s & 1) ? g_sA : g_sB;
            if (b > off) {
                int wk, koff;
                const float* krow;
                if (s == 0) { wk = g_Kwk[GLEN]; koff = g_Koff[GLEN]; krow = g_Kt + (GLEN - 1) * 256; }
                else        { wk = g_K2wk[s - 1]; koff = g_K2off[s - 1]; krow = g_Kt2 + (s - 1) * 384; }
                for (int p = t; p < wk; p += 256) Ks[p] = krow[p];
                for (int p = t; p < W; p += 256)
                    f_write(f, p, __ldcg(src + (size_t)(b - off) * WP + p));
                __syncthreads();
                int o0 = t * 4;
                if (o0 < W) {
                    float acc[4];
                    #pragma unroll
                    for (int e = 0; e < 4; e++) acc[e] = __ldcg(src + (size_t)b * WP + o0 + e);
                    conv_into(f, Ks, wk, koff, o0, acc);
                    #pragma unroll
                    for (int e = 0; e < 4; e++)
                        if (o0 + e < W) dst[(size_t)b * WP + o0 + e] = acc[e];
                }
                __syncthreads();
            } else {
                for (int p = t; p < W; p += 256)
                    dst[(size_t)b * WP + p] = __ldcg(src + (size_t)b * WP + p);
            }
        }
        gbar(CBLK * (2 + s));
    }

    // ---------------- phase C: correct chunks 19..148 (X in g_sB)
    {
        int c = GLEN + b;
        int g = c / GLEN, r = c - g * GLEN;

        if (r == 0) {
            for (int p = t; p < W; p += 256)
                g_vstart[(size_t)c * WP + p] = __ldcg(g_sB + (size_t)g * WP + p);
            return;
        }

        int wk = g_Kwk[r], off = g_Koff[r];
        for (int p = t; p < wk; p += 256) Ks[p] = g_Kt[(r - 1) * 256 + p];
        for (int p = t; p < W; p += 256)
            f_write(f, p, __ldcg(g_sB + (size_t)g * WP + p));
        __syncthreads();

        int o0 = t * 4;
        if (o0 < W) {
            float* vp = g_vstart + (size_t)c * WP + o0;
            float acc[4];
            #pragma unroll
            for (int e = 0; e < 4; e++) acc[e] = __ldcg(vp + e);
            conv_into(f, Ks, wk, off, o0, acc);
            #pragma unroll
            for (int e = 0; e < 4; e++)
                if (o0 + e < W) vp[e] = acc[e];
        }
    }
}

// ============================================================
// Kernel 3: karplus pass 2 (replay from exact starts)
// ============================================================
__global__ void __launch_bounds__(896) ks_pass2(const float* __restrict__ uscr) {
    __shared__ float bsh[2][W];
    __shared__ float ush[2][W];
    int c = blockIdx.x, i = threadIdx.x;
    if (c == 0 && i == 0) g_bar = 0;       // reset for bq_all
    bool act = i < W;
    int im1 = (i == 0) ? (W - 1) : (i - 1);
    int im2 = (i <= 1) ? (i + W - 2) : (i - 2);
    float d2 = g_par[0];

    float a = act ? g_vstart[(size_t)c * WP + i] : 0.0f;
    __syncthreads();

    const float* up = uscr + (size_t)c * MCH * W + i;
    float*       op = g_ks + (size_t)c * MCH * W + i;

    if (c < NCH - 1) {
        ks_run2<MCH / 2, false>(up, nullptr, op, a, bsh, ush, act, i, im1, im2, d2, 0.f);
    } else {
        ks_run2<LASTS / 2, false>(up, nullptr, op, a, bsh, ush, act, i, im1, im2, d2, 0.f);
        __syncthreads();
        if (act) bsh[0][i] = a;
        __syncthreads();
        if (i < REM) {
            float fin = d2 * (bsh[0][i] + bsh[0][im1]);
            int g = NB * W + i;
            if (g >= N_TOT - 256) fin *= (float)(N_TOT - 1 - g) * (1.0f / 255.0f);
            g_ks[g] = fin;
        }
    }
}

// ============================================================
// Kernel 4: fused band-reject (passA + hierarchical scan + passB)
// 128 blocks x 1024 threads; chunk = b*1024 + t, LBQ=64.
// ============================================================
__global__ void __launch_bounds__(1024) bq_all(float* __restrict__ out) {
    __shared__ float2 dsh[BQT];
    __shared__ float2 sv[BQT];
    __shared__ float2 cb[BQB];
    int b = blockIdx.x, t = threadIdx.x;

    float b0 = g_par[2], b1 = g_par[3], b2 = g_par[4], a1 = g_par[5], a2 = g_par[6];
    int chunk = b * BQT + t;
    size_t s0 = (size_t)chunk * LBQ;
    const float4* kp = (const float4*)(g_ks + s0);

    // ---- phase A: zero-init chunk end-state
    {
        float x1 = chunk ? g_ks[s0 - 1] : 0.0f;
        float x2 = chunk ? g_ks[s0 - 2] : 0.0f;
        float y1 = 0.0f, y2 = 0.0f;
        #pragma unroll 4
        for (int q = 0; q < LBQ / 4; q++) {
            float4 v = kp[q];
            float xs[4] = {v.x, v.y, v.z, v.w};
            #pragma unroll
            for (int e = 0; e < 4; e++) {
                float xn = xs[e];
                float cn = b0 * xn + b1 * x1 + b2 * x2;
                float yn = cn - a1 * y1 - a2 * y2;
                x2 = x1; x1 = xn; y2 = y1; y1 = yn;
            }
        }
        dsh[t] = make_float2(y1, y2);
        sv[t]  = make_float2(y1, y2);
    }
    __syncthreads();

    // ---- scan #1: in-block KS over 1024 zero-init states
    for (int s = 0; s < 10; s++) {
        int off = 1 << s;
        float A00 = (float)g_Ms[s][0], A01 = (float)g_Ms[s][1];
        float A10 = (float)g_Ms[s][2], A11 = (float)g_Ms[s][3];
        float ax = 0.f, ay = 0.f;
        if (t >= off) {
            float2 src = sv[t - off];
            ax = A00 * src.x + A01 * src.y;
            ay = A10 * src.x + A11 * src.y;
        }
        __syncthreads();
        sv[t].x += ax; sv[t].y += ay;
        __syncthreads();
    }
    if (t == BQT - 1) g_blk[b] = sv[BQT - 1];

    gbar(BQB);

    // ---- cross-block scan (redundant per block, 128 aggregates)
    if (t < BQB) { float2 v = g_blk[t]; cb[t] = make_float2(v.x, v.y); }
    __syncthreads();
    for (int s = 0; s < 7; s++) {
        int off = 1 << s;
        float A00 = (float)g_Ms[10 + s][0], A01 = (float)g_Ms[10 + s][1];
        float A10 = (float)g_Ms[10 + s][2], A11 = (float)g_Ms[10 + s][3];
        float ax = 0.f, ay = 0.f;
        if (t < BQB && t >= off) {
            float2 src = cb[t - off];
            ax = A00 * src.x + A01 * src.y;
            ay = A10 * src.x + A11 * src.y;
        }
        __syncthreads();
        if (t < BQB) { cb[t].x += ax; cb[t].y += ay; }
        __syncthreads();
    }
    float px = (b > 0) ? cb[b - 1].x : 0.0f;
    float py = (b > 0) ? cb[b - 1].y : 0.0f;
    __syncthreads();

    // ---- scan #2: seeded ([P, d_0, ..., d_1022]); sv[t] = start of chunk t
    sv[t] = (t == 0) ? make_float2(px, py) : dsh[t - 1];
    __syncthreads();
    for (int s = 0; s < 10; s++) {
        int off = 1 << s;
        float A00 = (float)g_Ms[s][0], A01 = (float)g_Ms[s][1];
        float A10 = (float)g_Ms[s][2], A11 = (float)g_Ms[s][3];
        float ax = 0.f, ay = 0.f;
        if (t >= off) {
            float2 src = sv[t - off];
            ax = A00 * src.x + A01 * src.y;
            ay = A10 * src.x + A11 * src.y;
        }
        __syncthreads();
        sv[t].x += ax; sv[t].y += ay;
        __syncthreads();
    }

    // ---- phase B: replay with exact start + fused envelope
    {
        float ia = g_par[7], ir = g_par[8], sg = g_par[9];
        float x1 = chunk ? g_ks[s0 - 1] : 0.0f;
        float x2 = chunk ? g_ks[s0 - 2] : 0.0f;
        float y1 = sv[t].x, y2 = sv[t].y;
        float4* op = (float4*)(out + s0);
        #pragma unroll 4
        for (int q = 0; q < LBQ / 4; q++) {
            float4 v = kp[q];
            float xs[4] = {v.x, v.y, v.z, v.w};
            float ys[4];
            int n0 = (int)s0 + q * 4;
            #pragma unroll
            for (int e = 0; e < 4; e++) {
                float xn = xs[e];
                float cn = b0 * xn + b1 * x1 + b2 * x2;
                float yn = cn - a1 * y1 - a2 * y2;
                x2 = x1; x1 = xn; y2 = y1; y1 = yn;
                float fn = (float)(n0 + e);
                float e1 = fminf(fn * ia, 1.0f);
                float e2 = fminf(((float)(N_TOT - 1) - fn) * ir, 1.0f);
                ys[e] = yn * e1 * e2 * sg;
            }
            op[q] = make_float4(ys[0], ys[1], ys[2], ys[3]);
        }
    }
}

// ============================================================
extern "C" void kernel_launch(void* const* d_in, const int* in_sizes, int n_in,
                              void* d_out, int out_size) {
    const float* fb  = (const float*)d_in[0];
    const float* wt  = (const float*)d_in[1];
    const float* h   = (const float*)d_in[2];
    const float* ep  = (const float*)d_in[3];
    const float* lp2 = (const float*)d_in[4];
    float* out = (float*)d_out;

    ks1_prep<<<PREPB + NCH, 896>>>(fb, out, wt, h, ep, lp2);   // u -> out (scratch)
    ks_combine_all<<<CBLK, 256>>>();
    ks_pass2<<<NCH, 896>>>(out);
    bq_all<<<BQB, 1024>>>(out);
}

// round 8
// speedup vs baseline: 1.2683x; 1.2683x over previous
#include <cuda_runtime.h>
#include <math.h>

#ifndef M_PI
#define M_PI 3.14159265358979323846
#endif

#define N_TOT   8388608
#define W       882
#define WP      884
#define NB      9510
#define REM     788
#define MCH     64
#define NCH     149
#define LASTS   38
#define GLEN    19
#define NG      8
#define AOFF    860
#define FSZ     1756
#define SRATE   44100.0
#define PREPB   9
#define CBLK    130

// band-reject geometry
#define LBQ     64            // samples per chunk
#define BQW     4             // warps per block
#define BQTH    128           // threads per block (= chunks per block)
#define SLAB    2080          // 32*65 floats per warp slab
#define SPB     8192          // samples per block (128 chunks * 64)
#define NBQB    1024          // blocks (N_TOT / SPB)

// ---- scratch ----
__device__ float  g_wt[W];
__device__ float  g_dstate[NCH * WP];
__device__ float  g_vstart[NCH * WP];
__device__ float  g_sA[NG * WP];
__device__ float  g_sB[NG * WP];
__device__ float  g_ks[N_TOT];
__device__ float2 g_blk[NBQB];
__device__ float2 g_blkP[NBQB];
__device__ float  g_MsF[18][4];          // M^(64 * 2^s), s=0..17 (f32)
__device__ float  g_par[12];             // 0:d2 1:fa2 2..6:bq 7:ia 8:ir 9:sg
__device__ float  g_Kt[GLEN * 256];      // reversed taps S^(64k), k=1..19
__device__ float  g_Kt2[2 * 384];        // k=38, k=76
__device__ int    g_Kwk[GLEN + 1], g_Koff[GLEN + 1];
__device__ int    g_K2wk[2], g_K2off[2];
__device__ unsigned g_bar;

// ---- grid barrier (combine kernel only; grid <= 148) ----
__device__ __forceinline__ void gbar(unsigned target) {
    __threadfence();
    __syncthreads();
    if (threadIdx.x == 0) {
        atomicAdd(&g_bar, 1u);
        while (*(volatile unsigned*)&g_bar < target) { }
    }
    __syncthreads();
    __threadfence();
}

// geometry of truncated kernel for S^(64k), window folded mod W
__device__ __forceinline__ void kgeom2(int k, int& c0e, int& wk, int& jb) {
    int m = 64 * k;
    int hw = (int)ceil(21.0 * sqrt((double)k));
    int c0 = m / 2 - hw;
    wk = (2 * hw + 4) & ~3;
    int red = (c0 / W) * W;
    int ce = c0 - red;
    ce -= (ce + wk - 1) & 3;       // force (ce+wk) % 4 == 1
    c0e = ce;
    jb = ce + red;
}

__device__ __forceinline__ float ftanh2(float x2) {
    float e = __expf(x2);
    return __fdividef(e - 1.0f, e + 1.0f);
}

// 2x2 matrix helpers over g_MsF
__device__ __forceinline__ void mload(int s, float& A, float& B, float& C, float& D) {
    A = g_MsF[s][0]; B = g_MsF[s][1]; C = g_MsF[s][2]; D = g_MsF[s][3];
}
// M^(64*e), e >= 0, via binary composition (all powers of M commute)
__device__ __forceinline__ void mpow64(int e, float& ra, float& rb, float& rc, float& rd) {
    ra = 1.f; rb = 0.f; rc = 0.f; rd = 1.f;
    for (int s = 0; e; s++, e >>= 1) {
        if (e & 1) {
            float A, B, C, D; mload(s, A, B, C, D);
            float na = A * ra + B * rc, nb = A * rb + B * rd;
            float nc = C * ra + D * rc, nd = C * rb + D * rd;
            ra = na; rb = nb; rc = nc; rd = nd;
        }
    }
}

// f[] circular extension: f[t] = v[(t - AOFF) mod W], t in [0, FSZ)
__device__ __forceinline__ void f_write(float* f, int p, float v) {
    f[p + AOFF] = v;
    if (p >= W - AOFF) f[p - (W - AOFF)] = v;
    if (p < FSZ - (W + AOFF)) f[p + W + AOFF] = v;
}

__device__ __forceinline__ void conv_into(const float* __restrict__ f,
                                          const float* __restrict__ Ks,
                                          int wk, int off, int o0, float* acc) {
    int b0 = o0 + off;
    float4 da = *(const float4*)&f[b0];
    #pragma unroll 2
    for (int jj = 0; jj < wk; jj += 4) {
        float4 ka = *(const float4*)&Ks[jj];
        float4 db = *(const float4*)&f[b0 + jj + 4];
        acc[0] = fmaf(ka.x, da.x, acc[0]); acc[0] = fmaf(ka.y, da.y, acc[0]);
        acc[0] = fmaf(ka.z, da.z, acc[0]); acc[0] = fmaf(ka.w, da.w, acc[0]);
        acc[1] = fmaf(ka.x, da.y, acc[1]); acc[1] = fmaf(ka.y, da.z, acc[1]);
        acc[1] = fmaf(ka.z, da.w, acc[1]); acc[1] = fmaf(ka.w, db.x, acc[1]);
        acc[2] = fmaf(ka.x, da.z, acc[2]); acc[2] = fmaf(ka.y, da.w, acc[2]);
        acc[2] = fmaf(ka.z, db.x, acc[2]); acc[2] = fmaf(ka.w, db.y, acc[2]);
        acc[3] = fmaf(ka.x, da.w, acc[3]); acc[3] = fmaf(ka.y, db.x, acc[3]);
        acc[3] = fmaf(ka.z, db.y, acc[3]); acc[3] = fmaf(ka.w, db.z, acc[3]);
        da = db;
    }
}

// ============================================================
// Karplus runner (2 steps / barrier round)
// ============================================================
template<int NR, bool P1>
__device__ __forceinline__ void ks_run2(const float* __restrict__ xin,
                                        float* __restrict__ uout,
                                        float* __restrict__ op,
                                        float& a,
                                        float (*bsh)[W], float (*ush)[W],
                                        bool act, int i, int im1, int im2,
                                        float d2, float fa2) {
    float xa[2], xb[2];
    #pragma unroll
    for (int q = 0; q < 2; q++) {
        xa[q] = act ? xin[(size_t)(2 * q) * W] : 0.f;
        xb[q] = act ? xin[(size_t)(2 * q + 1) * W] : 0.f;
    }
    #pragma unroll 2
    for (int r = 0; r < NR; r++) {
        float x0 = xa[r & 1], x1 = xb[r & 1];
        if (act && r + 2 < NR) {
            xa[r & 1] = xin[(size_t)(2 * r + 4) * W];
            xb[r & 1] = xin[(size_t)(2 * r + 5) * W];
        }
        float u0, u1;
        if (P1) {
            u0 = ftanh2(fa2 * x0);
            u1 = ftanh2(fa2 * x1);
            if (act) {
                uout[(size_t)(2 * r) * W] = u0;
                uout[(size_t)(2 * r + 1) * W] = u1;
            }
        } else { u0 = x0; u1 = x1; }

        float bb = a + u0;
        if (act) { bsh[r & 1][i] = bb; ush[r & 1][i] = u1; }
        __syncthreads();
        if (act) {
            float bm1 = bsh[r & 1][im1], bm2 = bsh[r & 1][im2];
            float u1m1 = ush[r & 1][im1];
            float a1  = d2 * (bb + bm1);
            float a1m = d2 * (bm1 + bm2);
            float a2  = d2 * ((a1 + u1) + (a1m + u1m1));
            if (!P1) {
                op[(size_t)(2 * r) * W] = a1;
                op[(size_t)(2 * r + 1) * W] = a2;
            }
            a = a2;
        }
    }
}

// ============================================================
// Kernel 1: fused prep (blocks 0..8) + ks_pass1 (blocks 9..157)
// ============================================================
struct SmemP1 { float bsh[2][W]; float ush[2][W]; };
struct SmemWT { float xs[898]; float ys[898]; float2 sv[128]; float Pw[7][4]; float cf[10]; };

__global__ void __launch_bounds__(896) ks1_prep(const float* __restrict__ fb,
                                                float* __restrict__ uscr,
                                                const float* __restrict__ wavetable,
                                                const float* __restrict__ h,
                                                const float* __restrict__ envp,
                                                const float* __restrict__ lp2) {
    __shared__ union { SmemP1 p1; SmemWT wt; } sm;
    int b = blockIdx.x, t = threadIdx.x;

    if (b >= PREPB) {
        int c = b - PREPB;
        int i = t;
        bool act = i < W;
        int im1 = (i == 0) ? (W - 1) : (i - 1);
        int im2 = (i <= 1) ? (i + W - 2) : (i - 2);
        float dec = fminf(fmaxf(h[0] * 0.1f + 0.9f, 0.9f), 0.999f);
        float d2 = dec * 0.5f;
        float fa2 = 2.0f * h[3];

        float a = 0.0f;
        const float* fp = fb   + (size_t)c * MCH * W + i;
        float*       up = uscr + (size_t)c * MCH * W + i;
        if (c < NCH - 1) {
            ks_run2<MCH / 2, true>(fp, up, nullptr, a, sm.p1.bsh, sm.p1.ush,
                                   act, i, im1, im2, d2, fa2);
            if (act) g_dstate[c * WP + i] = a;
        } else {
            ks_run2<LASTS / 2, true>(fp, up, nullptr, a, sm.p1.bsh, sm.p1.ush,
                                     act, i, im1, im2, d2, fa2);
        }
        return;
    }

    if (b >= 2 && b <= 7) {
        int idx = (b - 2) * 896 + t;
        if (idx < GLEN * 256) {
            double decay = (double)h[0] / 10.0 + 0.9;
            decay = fmin(fmax(decay, 0.9), 0.999);
            double ld2 = log(decay * 0.5);
            int k = idx / 256 + 1;
            int jj = idx % 256;
            int c0e, wk, jb; kgeom2(k, c0e, wk, jb);
            int m = 64 * k;
            float val = 0.0f;
            if (jj < wk) {
                int j = jb + wk - 1 - jj;
                if (j >= 0 && j <= m) {
                    double lg = lgamma((double)(m + 1)) - lgamma((double)(j + 1))
                              - lgamma((double)(m - j + 1)) + (double)m * ld2;
                    val = (float)exp(lg);
                }
            }
            g_Kt[idx] = val;
        }
        return;
    }

    if (b == 8) {
        int idx = t;
        if (idx < 2 * 384) {
            double decay = (double)h[0] / 10.0 + 0.9;
            decay = fmin(fmax(decay, 0.9), 0.999);
            double ld2 = log(decay * 0.5);
            int s = idx / 384;
            int jj = idx % 384;
            int k = 38 << s;
            int c0e, wk, jb; kgeom2(k, c0e, wk, jb);
            int m = 64 * k;
            float val = 0.0f;
            if (jj < wk) {
                int j = jb + wk - 1 - jj;
                if (j >= 0 && j <= m) {
                    double lg = lgamma((double)(m + 1)) - lgamma((double)(j + 1))
                              - lgamma((double)(m - j + 1)) + (double)m * ld2;
                    val = (float)exp(lg);
                }
            }
            g_Kt2[idx] = val;
        }
        return;
    }

    if (b == 0) {
        if (t >= 1 && t <= GLEN) {
            int c0e, wk, jb; kgeom2(t, c0e, wk, jb);
            g_Kwk[t] = wk;
            g_Koff[t] = AOFF + 1 - c0e - wk;
        }
        if (t == 20 || t == 21) {
            int lvl = t - 20;
            int c0e, wk, jb; kgeom2(38 << lvl, c0e, wk, jb);
            g_K2wk[lvl] = wk;
            g_K2off[lvl] = AOFF + 1 - c0e - wk;
        }
        if (t != 0) return;

        g_bar = 0;

        double decay = (double)h[0] / 10.0 + 0.9;
        decay = fmin(fmax(decay, 0.9), 0.999);

        double h5 = h[5], h6 = h[6];
        double brf = h5 * SRATE / 4.0; brf = fmin(fmax(brf, 100.0), SRATE / 2.0 - 1.0);
        double brq = fmin(fmax(h6, 0.1), 0.999);
        double w0b = 2.0 * M_PI * brf / SRATE, alb = sin(w0b) / (2.0 * brq), cwb = cos(w0b);
        double a0b = 1.0 + alb;
        double bb0 = 1.0 / a0b, bb1 = (-2.0 * cwb) / a0b, bb2 = 1.0 / a0b;
        double ba1 = (-2.0 * cwb) / a0b, ba2 = (1.0 - alb) / a0b;

        // M^(64 * 2^s), s=0..17 (store f32)
        {
            double m00 = -ba1, m01 = -ba2, m10 = 1.0, m11 = 0.0;
            for (int s = 0; s < 6; s++) {                    // -> M^64
                double n00 = m00 * m00 + m01 * m10, n01 = m00 * m01 + m01 * m11;
                double n10 = m10 * m00 + m11 * m10, n11 = m10 * m01 + m11 * m11;
                m00 = n00; m01 = n01; m10 = n10; m11 = n11;
            }
            for (int s = 0; s < 18; s++) {
                g_MsF[s][0] = (float)m00; g_MsF[s][1] = (float)m01;
                g_MsF[s][2] = (float)m10; g_MsF[s][3] = (float)m11;
                double n00 = m00 * m00 + m01 * m10, n01 = m00 * m01 + m01 * m11;
                double n10 = m10 * m00 + m11 * m10, n11 = m10 * m01 + m11 * m11;
                m00 = n00; m01 = n01; m10 = n10; m11 = n11;
            }
        }

        double nD = (double)N_TOT;
        double attack  = 1.0 + (double)envp[0] * 0.1 * nD;
        double release = 1.0 + (double)envp[2] * 0.1 * nD;
        double sustain = fmin(fmax((double)envp[1], 0.0), 1.0);

        g_par[0] = (float)(decay * 0.5);
        g_par[1] = (float)(2.0 * (double)h[3]);
        g_par[2] = (float)bb0; g_par[3] = (float)bb1; g_par[4] = (float)bb2;
        g_par[5] = (float)ba1; g_par[6] = (float)ba2;
        g_par[7] = (float)(1.0 / attack);
        g_par[8] = (float)(1.0 / release);
        g_par[9] = (float)(sustain * (double)h[4]);
        return;
    }

    // ---------------- b == 1: wavetable prefilter
    {
        float* xs = sm.wt.xs; float* ys = sm.wt.ys;
        float2* sv = sm.wt.sv; float (*Pw)[4] = sm.wt.Pw; float* cf = sm.wt.cf;

        if (t < 128)
            for (int p = t; p < 896; p += 128) xs[2 + p] = (p < W) ? wavetable[p] : 0.0f;
        if (t < 2) { xs[t] = 0.0f; ys[t] = 0.0f; }

        if (t == 0) {
            double h1 = h[1], h2 = h[2];
            double lpf = h1 * SRATE / 4.0; lpf = fmin(fmax(lpf, 100.0), SRATE / 2.0 - 1.0);
            double lpq = fmin(fmax(h2, 0.1), 0.999);
            double w0 = 2.0 * M_PI * lpf / SRATE, al = sin(w0) / (2.0 * lpq), cw = cos(w0);
            double a0 = 1.0 + al;
            cf[0] = (float)(((1.0 - cw) * 0.5) / a0);
            cf[1] = (float)((1.0 - cw) / a0);
            cf[2] = cf[0];
            cf[3] = (float)((-2.0 * cw) / a0);
            cf[4] = (float)((1.0 - al) / a0);
            double c2 = 100.0 + (double)lp2[0] * 8000.0;
            double w02 = 2.0 * M_PI * c2 / SRATE, al2 = sin(w02) / (2.0 * 0.707), cw2 = cos(w02);
            double a02 = 1.0 + al2;
            cf[5] = (float)(((1.0 - cw2) * 0.5) / a02);
            cf[6] = (float)((1.0 - cw2) / a02);
            cf[7] = cf[5];
            cf[8] = (float)((-2.0 * cw2) / a02);
            cf[9] = (float)((1.0 - al2) / a02);
        }
        __syncthreads();

        #pragma unroll
        for (int f = 0; f < 2; f++) {
            float b0 = cf[5 * f + 0], b1 = cf[5 * f + 1], b2 = cf[5 * f + 2];
            float a1 = cf[5 * f + 3], a2 = cf[5 * f + 4];
            const float* in = (f == 0) ? xs : ys;
            int base = 2 + 7 * (t & 127);

            if (t < 128) {
                float y1 = 0.f, y2 = 0.f;
                #pragma unroll
                for (int i = 0; i < 7; i++) {
                    float cn = b0 * in[base + i] + b1 * in[base + i - 1] + b2 * in[base + i - 2];
                    float yn = cn - a1 * y1 - a2 * y2;
                    y2 = y1; y1 = yn;
                }
                sv[t] = make_float2(y1, y2);
            }
            if (t == 0) {
                double A00 = -(double)a1, A01 = -(double)a2, A10 = 1.0, A11 = 0.0;
                double q00 = A00*A00 + A01*A10, q01 = A00*A01 + A01*A11;
                double q10 = A10*A00 + A11*A10, q11 = A10*A01 + A11*A11;
                double r00 = q00*q00 + q01*q10, r01 = q00*q01 + q01*q11;
                double r10 = q10*q00 + q11*q10, r11 = q10*q01 + q11*q11;
                double s00 = r00*q00 + r01*q10, s01 = r00*q01 + r01*q11;
                double s10 = r10*q00 + r11*q10, s11 = r10*q01 + r11*q11;
                double m00 = s00*A00 + s01*A10, m01 = s00*A01 + s01*A11;
                double m10 = s10*A00 + s11*A10, m11 = s10*A01 + s11*A11;
                for (int s = 0; s < 7; s++) {
                    Pw[s][0] = (float)m00; Pw[s][1] = (float)m01;
                    Pw[s][2] = (float)m10; Pw[s][3] = (float)m11;
                    double n00 = m00*m00 + m01*m10, n01 = m00*m01 + m01*m11;
                    double n10 = m10*m00 + m11*m10, n11 = m10*m01 + m11*m11;
                    m00 = n00; m01 = n01; m10 = n10; m11 = n11;
                }
            }
            __syncthreads();

            for (int s = 0; s < 7; s++) {
                int off = 1 << s;
                float ax = 0.f, ay = 0.f;
                if (t < 128 && t >= off) {
                    float2 src = sv[t - off];
                    ax = Pw[s][0] * src.x + Pw[s][1] * src.y;
                    ay = Pw[s][2] * src.x + Pw[s][3] * src.y;
                }
                __syncthreads();
                if (t < 128) { sv[t].x += ax; sv[t].y += ay; }
                __syncthreads();
            }

            if (t < 128) {
                float py1 = 0.f, py2 = 0.f;
                if (t > 0) { py1 = sv[t - 1].x; py2 = sv[t - 1].y; }
                #pragma unroll
                for (int i = 0; i < 7; i++) {
                    float cn = b0 * in[base + i] + b1 * in[base + i - 1] + b2 * in[base + i - 2];
                    float yn = cn - a1 * py1 - a2 * py2;
                    py2 = py1; py1 = yn;
                    if (f == 0) ys[base + i] = yn;
                    else { int g = 7 * t + i; if (g < W) g_wt[g] = yn; }
                }
            }
            __syncthreads();
        }
    }
}

// ============================================================
// Kernel 2: fused combine (phase A + group KS-scan + phase C)
// ============================================================
__global__ void __launch_bounds__(256) ks_combine_all() {
    __shared__ __align__(16) float f[FSZ];
    __shared__ __align__(16) float Ks[384];
    int b = blockIdx.x, t = threadIdx.x;

    if (b < NG) {
        int g = b;
        for (int p = t; p < g_Kwk[1]; p += 256) Ks[p] = g_Kt[p];
        int wk = g_Kwk[1], off = g_Koff[1];
        int c1 = g * GLEN;
        int len = (g == NG - 1) ? (NCH - (NG - 1) * GLEN) : GLEN;
        int cend  = c1 + len;
        int cendT = (g == NG - 1) ? (NCH - 1) : cend;

        int cbeg;
        if (g == 0) {
            for (int p = t; p < W; p += 256) {
                float v = g_wt[p];
                f_write(f, p, v);
                g_vstart[p] = v;
            }
            cbeg = 1;
        } else {
            for (int p = t; p < W; p += 256) {
                float v = g_dstate[c1 * WP + p];
                f_write(f, p, v);
                g_vstart[(c1 + 1) * WP + p] = v;
            }
            cbeg = c1 + 2;
        }
        __syncthreads();

        int o0 = t * 4;
        bool activ = o0 < W;
        float4 dv = make_float4(0.f, 0.f, 0.f, 0.f);
        if (activ) dv = *(const float4*)(g_dstate + (size_t)(cbeg - 1) * WP + o0);

        for (int c = cbeg; c <= cendT; c++) {
            float4 dnext = make_float4(0.f, 0.f, 0.f, 0.f);
            if (activ && c <= cendT - 1)
                dnext = *(const float4*)(g_dstate + (size_t)c * WP + o0);

            float acc[4] = {dv.x, dv.y, dv.z, dv.w};
            if (activ) conv_into(f, Ks, wk, off, o0, acc);
            __syncthreads();
            if (activ) {
                float* dst;
                if (c < cend) dst = g_vstart + (size_t)c * WP + o0;
                else dst = g_sA + (size_t)(g + 1) * WP + o0;
                #pragma unroll
                for (int e = 0; e < 4; e++) {
                    int p = o0 + e;
                    if (p < W) { f_write(f, p, acc[e]); dst[e] = acc[e]; }
                }
            }
            __syncthreads();
            dv = dnext;
        }
    }
    gbar(CBLK);

    for (int s = 0; s < 3; s++) {
        int off = 1 << s;
        if (b >= 1 && b <= 7) {
            const float* src = (s & 1) ? g_sB : g_sA;
            float*       dst = (s & 1) ? g_sA : g_sB;
            if (b > off) {
                int wk, koff;
                const float* krow;
                if (s == 0) { wk = g_Kwk[GLEN]; koff = g_Koff[GLEN]; krow = g_Kt + (GLEN - 1) * 256; }
                else        { wk = g_K2wk[s - 1]; koff = g_K2off[s - 1]; krow = g_Kt2 + (s - 1) * 384; }
                for (int p = t; p < wk; p += 256) Ks[p] = krow[p];
                for (int p = t; p < W; p += 256)
                    f_write(f, p, __ldcg(src + (size_t)(b - off) * WP + p));
                __syncthreads();
                int o0 = t * 4;
                if (o0 < W) {
                    float acc[4];
                    #pragma unroll
                    for (int e = 0; e < 4; e++) acc[e] = __ldcg(src + (size_t)b * WP + o0 + e);
                    conv_into(f, Ks, wk, koff, o0, acc);
                    #pragma unroll
                    for (int e = 0; e < 4; e++)
                        if (o0 + e < W) dst[(size_t)b * WP + o0 + e] = acc[e];
                }
                __syncthreads();
            } else {
                for (int p = t; p < W; p += 256)
                    dst[(size_t)b * WP + p] = __ldcg(src + (size_t)b * WP + p);
            }
        }
        gbar(CBLK * (2 + s));
    }

    {
        int c = GLEN + b;
        int g = c / GLEN, r = c - g * GLEN;

        if (r == 0) {
            for (int p = t; p < W; p += 256)
                g_vstart[(size_t)c * WP + p] = __ldcg(g_sB + (size_t)g * WP + p);
            return;
        }

        int wk = g_Kwk[r], off = g_Koff[r];
        for (int p = t; p < wk; p += 256) Ks[p] = g_Kt[(r - 1) * 256 + p];
        for (int p = t; p < W; p += 256)
            f_write(f, p, __ldcg(g_sB + (size_t)g * WP + p));
        __syncthreads();

        int o0 = t * 4;
        if (o0 < W) {
            float* vp = g_vstart + (size_t)c * WP + o0;
            float acc[4];
            #pragma unroll
            for (int e = 0; e < 4; e++) acc[e] = __ldcg(vp + e);
            conv_into(f, Ks, wk, off, o0, acc);
            #pragma unroll
            for (int e = 0; e < 4; e++)
                if (o0 + e < W) vp[e] = acc[e];
        }
    }
}

// ============================================================
// Kernel 3: karplus pass 2
// ============================================================
__global__ void __launch_bounds__(896) ks_pass2(const float* __restrict__ uscr) {
    __shared__ float bsh[2][W];
    __shared__ float ush[2][W];
    int c = blockIdx.x, i = threadIdx.x;
    bool act = i < W;
    int im1 = (i == 0) ? (W - 1) : (i - 1);
    int im2 = (i <= 1) ? (i + W - 2) : (i - 2);
    float d2 = g_par[0];

    float a = act ? g_vstart[(size_t)c * WP + i] : 0.0f;
    __syncthreads();

    const float* up = uscr + (size_t)c * MCH * W + i;
    float*       op = g_ks + (size_t)c * MCH * W + i;

    if (c < NCH - 1) {
        ks_run2<MCH / 2, false>(up, nullptr, op, a, bsh, ush, act, i, im1, im2, d2, 0.f);
    } else {
        ks_run2<LASTS / 2, false>(up, nullptr, op, a, bsh, ush, act, i, im1, im2, d2, 0.f);
        __syncthreads();
        if (act) bsh[0][i] = a;
        __syncthreads();
        if (i < REM) {
            float fin = d2 * (bsh[0][i] + bsh[0][im1]);
            int g = NB * W + i;
            if (g >= N_TOT - 256) fin *= (float)(N_TOT - 1 - g) * (1.0f / 255.0f);
            g_ks[g] = fin;
        }
    }
}

// ============================================================
// Band-reject shared machinery: coalesced slab load + zero-run
// + in-warp shuffle scan. Slab layout: lane c chunk at c*65+k.
// ============================================================
__device__ __forceinline__ void bq_load_slab(float* sl, int b, int w, int l) {
    const float4* gp = (const float4*)(g_ks + (size_t)b * SPB + (size_t)w * 2048);
    #pragma unroll
    for (int i = 0; i < 16; i++) {
        float4 v = gp[i * 32 + l];
        int s4 = i * 128 + l * 4;
        int c = s4 >> 6, k = s4 & 63;
        float* q = sl + c * 65 + k;
        q[0] = v.x; q[1] = v.y; q[2] = v.z; q[3] = v.w;
    }
}

// zero-init chunk run + in-warp KS scan; returns inclusive state v
// and this chunk's (x1,x2) history.
__device__ __forceinline__ float2 bq_zero_scan(const float* slab, int b, int t,
                                               int w, int l,
                                               float b0, float b1, float b2,
                                               float a1, float a2,
                                               float& hx1, float& hx2) {
    if (t == 0) {
        size_t s0 = (size_t)b * SPB;
        hx1 = b ? g_ks[s0 - 1] : 0.f;
        hx2 = b ? g_ks[s0 - 2] : 0.f;
    } else {
        int pw = (t - 1) >> 5, pl = (t - 1) & 31;
        const float* pv = slab + pw * SLAB + pl * 65;
        hx1 = pv[63]; hx2 = pv[62];
    }
    const float* cp = slab + w * SLAB + l * 65;
    float x1 = hx1, x2 = hx2, y1 = 0.f, y2 = 0.f;
    #pragma unroll
    for (int k = 0; k < 64; k++) {
        float xn = cp[k];
        float yn = fmaf(b0, xn, fmaf(b1, x1, b2 * x2)) - fmaf(a1, y1, a2 * y2);
        x2 = x1; x1 = xn; y2 = y1; y1 = yn;
    }
    float2 v = make_float2(y1, y2);
    #pragma unroll
    for (int s = 0; s < 5; s++) {
        int off = 1 << s;
        float px = __shfl_up_sync(0xffffffffu, v.x, off);
        float py = __shfl_up_sync(0xffffffffu, v.y, off);
        if (l >= off) {
            float A, B, C, D; mload(s, A, B, C, D);
            v.x = fmaf(A, px, fmaf(B, py, v.x));
            v.y = fmaf(C, px, fmaf(D, py, v.y));
        }
    }
    return v;
}

// ============================================================
// Kernel 4: bq pass A — block aggregates only
// ============================================================
__global__ void __launch_bounds__(BQTH) bq_passA() {
    __shared__ __align__(16) float slab[BQW * SLAB];
    __shared__ float2 wag[BQW];
    int b = blockIdx.x, t = threadIdx.x, w = t >> 5, l = t & 31;
    float b0 = g_par[2], b1 = g_par[3], b2 = g_par[4], a1 = g_par[5], a2 = g_par[6];

    bq_load_slab(slab + w * SLAB, b, w, l);
    __syncthreads();

    float hx1, hx2;
    float2 v = bq_zero_scan(slab, b, t, w, l, b0, b1, b2, a1, a2, hx1, hx2);
    if (l == 31) wag[w] = v;
    __syncthreads();

    if (t == BQTH - 1) {
        float A, B, C, D; mload(5, A, B, C, D);   // M^2048
        float2 P = wag[0];
        #pragma unroll
        for (int u = 1; u < BQW; u++) {
            float2 nw = wag[u];
            P = make_float2(nw.x + A * P.x + B * P.y, nw.y + C * P.x + D * P.y);
        }
        g_blk[b] = P;
    }
}

// ============================================================
// Kernel 5: cross-block scan over 1024 aggregates -> exclusive
// ============================================================
__global__ void __launch_bounds__(1024) bq_scanK() {
    __shared__ float2 sv[NBQB];
    int t = threadIdx.x;
    sv[t] = g_blk[t];
    __syncthreads();
    for (int s = 0; s < 10; s++) {
        int off = 1 << s;
        float A, B, C, D; mload(7 + s, A, B, C, D);   // M^(8192*2^s)
        float ax = 0.f, ay = 0.f;
        if (t >= off) {
            float2 sr = sv[t - off];
            ax = fmaf(A, sr.x, B * sr.y);
            ay = fmaf(C, sr.x, D * sr.y);
        }
        __syncthreads();
        sv[t].x += ax; sv[t].y += ay;
        __syncthreads();
    }
    g_blkP[t] = t ? sv[t - 1] : make_float2(0.f, 0.f);
}

// ============================================================
// Kernel 6: bq pass B — exact replay + envelope, staged I/O
// ============================================================
__global__ void __launch_bounds__(BQTH) bq_passB(float* __restrict__ out) {
    __shared__ __align__(16) float slab[BQW * SLAB];
    __shared__ float2 wag[BQW];
    int b = blockIdx.x, t = threadIdx.x, w = t >> 5, l = t & 31;
    float b0 = g_par[2], b1 = g_par[3], b2 = g_par[4], a1 = g_par[5], a2 = g_par[6];

    bq_load_slab(slab + w * SLAB, b, w, l);
    __syncthreads();

    float hx1, hx2;
    float2 v = bq_zero_scan(slab, b, t, w, l, b0, b1, b2, a1, a2, hx1, hx2);
    if (l == 31) wag[w] = v;
    __syncthreads();

    // warp prefix within block
    float2 P = make_float2(0.f, 0.f);
    {
        float A, B, C, D; mload(5, A, B, C, D);
        for (int u = 0; u < w; u++) {
            float2 nw = wag[u];
            P = make_float2(nw.x + A * P.x + B * P.y, nw.y + C * P.x + D * P.y);
        }
    }
    // exclusive within warp
    float ex = __shfl_up_sync(0xffffffffu, v.x, 1);
    float ey = __shfl_up_sync(0xffffffffu, v.y, 1);
    if (l == 0) { ex = 0.f; ey = 0.f; }
    // E = e + M^(64*l) * P
    {
        float ra, rb, rc, rd; mpow64(l, ra, rb, rc, rd);
        ex += ra * P.x + rb * P.y;
        ey += rc * P.x + rd * P.y;
    }
    // S = E + M^(64*t) * P_block
    {
        float2 Pb = g_blkP[b];
        float ra, rb, rc, rd; mpow64(t, ra, rb, rc, rd);
        ex += ra * Pb.x + rb * Pb.y;
        ey += rc * Pb.x + rd * Pb.y;
    }

    // replay in-place with envelope
    {
        float ia = g_par[7], ir = g_par[8], sg = g_par[9];
        float* cp = slab + w * SLAB + l * 65;
        float x1 = hx1, x2 = hx2, y1 = ex, y2 = ey;
        size_t s0 = (size_t)b * SPB + (size_t)t * 64;
        #pragma unroll
        for (int k = 0; k < 64; k++) {
            float xn = cp[k];
            float yn = fmaf(b0, xn, fmaf(b1, x1, b2 * x2)) - fmaf(a1, y1, a2 * y2);
            x2 = x1; x1 = xn; y2 = y1; y1 = yn;
            float fn = (float)(s0 + k);
            float e1 = fminf(fn * ia, 1.0f);
            float e2 = fminf(((float)(N_TOT - 1) - fn) * ir, 1.0f);
            cp[k] = yn * e1 * e2 * sg;
        }
    }
    __syncwarp();

    // coalesced store
    {
        const float* sl = slab + w * SLAB;
        float4* op = (float4*)(out + (size_t)b * SPB + (size_t)w * 2048);
        #pragma unroll
        for (int i = 0; i < 16; i++) {
            int s4 = i * 128 + l * 4;
            int c = s4 >> 6, k = s4 & 63;
            const float* q = sl + c * 65 + k;
            op[i * 32 + l] = make_float4(q[0], q[1], q[2], q[3]);
        }
    }
}

// ============================================================
extern "C" void kernel_launch(void* const* d_in, const int* in_sizes, int n_in,
                              void* d_out, int out_size) {
    const float* fb  = (const float*)d_in[0];
    const float* wt  = (const float*)d_in[1];
    const float* h   = (const float*)d_in[2];
    const float* ep  = (const float*)d_in[3];
    const float* lp2 = (const float*)d_in[4];
    float* out = (float*)d_out;

    ks1_prep<<<PREPB + NCH, 896>>>(fb, out, wt, h, ep, lp2);   // u -> out (scratch)
    ks_combine_all<<<CBLK, 256>>>();
    ks_pass2<<<NCH, 896>>>(out);
    bq_passA<<<NBQB, BQTH>>>();
    bq_scanK<<<1, 1024>>>();
    bq_passB<<<NBQB, BQTH>>>(out);
}